// round 9
// baseline (speedup 1.0000x reference)
#include <cuda_runtime.h>
#include <cuda_bf16.h>
#include <mma.h>
#include <math.h>

using namespace nvcuda;

#define BB    2048
#define U1N   101
#define DN    128
#define STEPN 165
#define HN    200
#define IM1   63
#define NPAD  224          // padded N (200 -> 224, zeros beyond)

// ---------------------------------------------------------------------------
// scratch: W1e as B matrix, layout [n][k] (k contiguous) = col-major B, hi/lo
__device__ __nv_bfloat16 g_W1bfh[NPAD * DN];
__device__ __nv_bfloat16 g_W1bfl[NPAD * DN];
__device__ int g_mask_is_i32;

// ---------------------------------------------------------------------------
__global__ void flag_init_kernel() { g_mask_is_i32 = 1; }

__global__ __launch_bounds__(256) void mask_detect_kernel(const unsigned* __restrict__ m)
{
    int n = (BB * U1N) / 4;
    for (int idx = blockIdx.x * 256 + threadIdx.x; idx < n; idx += gridDim.x * 256) {
        if (m[idx] > 1u) { atomicExch(&g_mask_is_i32, 0); return; }
    }
}

// W1e -> bf16 hi/lo, transposed to [n][k]
__global__ __launch_bounds__(256) void w1bf_kernel(const float* __restrict__ W1)
{
    int idx = blockIdx.x * 256 + threadIdx.x;
    if (idx < NPAD * DN) {
        int n = idx / DN, k = idx % DN;
        float v = (n < HN) ? W1[(size_t)(130 + k) * HN + n] : 0.f;
        __nv_bfloat16 h = __float2bfloat16_rn(v);
        __nv_bfloat16 l = __float2bfloat16_rn(v - __bfloat162float(h));
        g_W1bfh[idx] = h;
        g_W1bfl[idx] = l;
    }
}

// ---------------------------------------------------------------------------
// dynamic smem layout:
//   [0      .. 32768)   A_hi  (128x128 bf16, row-major ld=128)
//   [32768  .. 65536)   A_lo
//   [65536  .. 90112)   prologue partials (3 x 16 x 32 float4)
//   -- after MMA, [0 .. 114688) is reused as P (128x224 f32, row-major) --
//   [114688 .. +Tail)   persistent small arrays
static const int OFF_AH   = 0;
static const int OFF_AL   = 32768;
static const int OFF_PART = 65536;
static const int OFF_TAIL = 114688;

struct Tail {
    float s_minc[128], s_memb[128], s_mhist[128], s_msel[128], s_sc[128];
    float s_scp[2][128];
    float s_bp[2][200];
    float s_base[224], s_w1r0[224], s_w2[224];
    float s_w[128];
    float s_pi[128];
    float s_lse;
    int   s_sel_idx;
};

// ---------------------------------------------------------------------------
__global__ __launch_bounds__(512, 1) void fused_kernel(
    const float* __restrict__ emb, const float* __restrict__ w,
    const float* __restrict__ W_sc, const float* __restrict__ b_sc,
    const float* __restrict__ W1, const float* __restrict__ b1,
    const float* __restrict__ W2, const float* __restrict__ b2,
    const int* __restrict__ seq, const void* __restrict__ mask,
    float* __restrict__ out, int mode)
{
    extern __shared__ char smem[];
    Tail* T = (Tail*)(smem + OFF_TAIL);
    __nv_bfloat16* A_hi = (__nv_bfloat16*)(smem + OFF_AH);
    __nv_bfloat16* A_lo = (__nv_bfloat16*)(smem + OFF_AL);
    float4* part = (float4*)(smem + OFF_PART);       // [3][16][32]
    float*  P    = (float*)smem;                     // post-MMA overlay

    int b    = blockIdx.x;
    int tid  = threadIdx.x;
    int lane = tid & 31;
    int wid  = tid >> 5;

    // ---- phase 0: small loads ----
    if (tid < 224) {
        T->s_w1r0[tid] = (tid < HN) ? W1[tid] : 0.f;
        T->s_w2[tid]   = (tid < HN) ? W2[tid] : 0.f;
    }
    if (tid >= 256 && tid < 384) {
        int u = tid - 256;
        T->s_w[u] = (u < U1N) ? w[b * U1N + u] : 0.f;
    }

    // ---- phase 1: emb pass (means + A hi/lo bf16 staging) + gather ----
    {
        int q = tid & 31;          // float4 column (k = 4q..4q+3)
        int h = tid >> 5;          // 0..15
        const float4* eb4 = (const float4*)(emb + (size_t)b * STEPN * DN);
        const float4* e4  = (const float4*)emb;

        float4 se = make_float4(0.f, 0.f, 0.f, 0.f);
        float4 sh = se, ss = se;
        for (int r = h; r < STEPN; r += 16) {
            float4 v = eb4[r * 32 + q];
            se.x += v.x; se.y += v.y; se.z += v.z; se.w += v.w;
            if (r >= 101 && r < 164) {
                sh.x += v.x; sh.y += v.y; sh.z += v.z; sh.w += v.w;
            }
            if (r == 164) ((float4*)T->s_minc)[q] = v;
            if (r < 128) {
                __nv_bfloat162 h01 = __floats2bfloat162_rn(v.x, v.y);
                __nv_bfloat162 h23 = __floats2bfloat162_rn(v.z, v.w);
                float lx = v.x - __bfloat162float(__low2bfloat16(h01));
                float ly = v.y - __bfloat162float(__high2bfloat16(h01));
                float lz = v.z - __bfloat162float(__low2bfloat16(h23));
                float lw = v.w - __bfloat162float(__high2bfloat16(h23));
                __nv_bfloat162 l01 = __floats2bfloat162_rn(lx, ly);
                __nv_bfloat162 l23 = __floats2bfloat162_rn(lz, lw);
                unsigned* dh = (unsigned*)&A_hi[r * DN + 4 * q];
                unsigned* dl = (unsigned*)&A_lo[r * DN + 4 * q];
                dh[0] = *(unsigned*)&h01; dh[1] = *(unsigned*)&h23;
                dl[0] = *(unsigned*)&l01; dl[1] = *(unsigned*)&l23;
            }
        }
        for (int j = h; j < IM1; j += 16) {
            int s = seq[b * IM1 + j];
            float4 v = e4[((size_t)b * IM1 + s) * 32 + q];  // deliberate cross-batch gather
            ss.x += v.x; ss.y += v.y; ss.z += v.z; ss.w += v.w;
        }
        part[0 * 512 + h * 32 + q] = se;
        part[1 * 512 + h * 32 + q] = sh;
        part[2 * 512 + h * 32 + q] = ss;
    }
    __syncthreads();

    // ---- phase 2: combine means ----
    if (tid < 128) {
        int d = tid;
        const float* pe = (const float*)&part[0];
        const float* ph = (const float*)&part[512];
        const float* ps = (const float*)&part[1024];
        float ae = 0.f, ah = 0.f, as = 0.f;
        #pragma unroll
        for (int g = 0; g < 16; ++g) {
            ae += pe[g * 128 + d]; ah += ph[g * 128 + d]; as += ps[g * 128 + d];
        }
        T->s_memb[d]  = ae * (1.f / STEPN);
        T->s_mhist[d] = ah * (1.f / IM1);
        T->s_msel[d]  = as * (1.f / IM1);
    }
    __syncthreads();

    // ---- phase 3: step_context ----
    if (tid < 256) {
        int g = tid >> 7, d = tid & 127;
        const float* vsrc = g ? T->s_mhist : T->s_msel;
        const float* wsrc = W_sc + (size_t)(g ? 128 : 0) * 128;
        float a0 = 0.f, a1 = 0.f;
        #pragma unroll 4
        for (int k = 0; k < 128; k += 2) {
            a0 = fmaf(vsrc[k],     wsrc[(k)     * 128 + d], a0);
            a1 = fmaf(vsrc[k + 1], wsrc[(k + 1) * 128 + d], a1);
        }
        T->s_scp[g][d] = a0 + a1;
    }
    __syncthreads();
    if (tid < 128) T->s_sc[tid] = T->s_scp[0][tid] + T->s_scp[1][tid] + b_sc[tid];
    __syncthreads();

    // ---- phase 4: base[o] ----
    {
        int o = tid & 255, g2 = tid >> 8;
        if (o < HN) {
            float a0, a1 = 0.f;
            if (g2 == 0) {
                a0 = b1[o] + 0.5f * W1[HN + o];   // idx feature = 64/128 = 0.5
                #pragma unroll 2
                for (int k = 0; k < 128; k += 2) {
                    a0 = fmaf(T->s_minc[k],     W1[(size_t)(2 + k) * HN + o], a0);
                    a1 = fmaf(T->s_minc[k + 1], W1[(size_t)(3 + k) * HN + o], a1);
                }
                #pragma unroll 2
                for (int k = 0; k < 64; ++k)
                    a0 = fmaf(T->s_sc[k], W1[(size_t)(258 + k) * HN + o], a0);
            } else {
                a0 = 0.f;
                #pragma unroll 2
                for (int k = 64; k < 128; ++k)
                    a0 = fmaf(T->s_sc[k], W1[(size_t)(258 + k) * HN + o], a0);
                #pragma unroll 2
                for (int k = 0; k < 128; k += 2) {
                    a0 = fmaf(T->s_memb[k],     W1[(size_t)(386 + k) * HN + o], a0);
                    a1 = fmaf(T->s_memb[k + 1], W1[(size_t)(387 + k) * HN + o], a1);
                }
            }
            T->s_bp[g2][o] = a0 + a1;
        }
    }
    __syncthreads();
    if (tid < 224) T->s_base[tid] = (tid < HN) ? (T->s_bp[0][tid] + T->s_bp[1][tid]) : 0.f;

    // ---- phase 5: tensor-core GEMM (wmma bf16, hi/lo 3-pass) ----
    // 16 warps = 8 M-tiles x 2 N-groups; each warp: 7 N-tiles of 16
    int mtile = wid >> 1;          // 0..7
    int grp   = wid & 1;           // 0..1
    int n0    = grp * 112;

    wmma::fragment<wmma::accumulator, 16, 16, 16, float> acc[7];
    #pragma unroll
    for (int j = 0; j < 7; ++j) wmma::fill_fragment(acc[j], 0.f);

    wmma::fragment<wmma::matrix_a, 16, 16, 16, __nv_bfloat16, wmma::row_major> a_h, a_l;
    wmma::fragment<wmma::matrix_b, 16, 16, 16, __nv_bfloat16, wmma::col_major> b_h, b_l;

    #pragma unroll 1
    for (int k = 0; k < 8; ++k) {
        const __nv_bfloat16* ah_p = A_hi + (mtile * 16) * DN + k * 16;
        const __nv_bfloat16* al_p = A_lo + (mtile * 16) * DN + k * 16;
        wmma::load_matrix_sync(a_h, ah_p, DN);
        wmma::load_matrix_sync(a_l, al_p, DN);
        #pragma unroll
        for (int j = 0; j < 7; ++j) {
            const __nv_bfloat16* bh_p = g_W1bfh + (size_t)(n0 + j * 16) * DN + k * 16;
            const __nv_bfloat16* bl_p = g_W1bfl + (size_t)(n0 + j * 16) * DN + k * 16;
            wmma::load_matrix_sync(b_h, bh_p, DN);
            wmma::load_matrix_sync(b_l, bl_p, DN);
            wmma::mma_sync(acc[j], a_h, b_h, acc[j]);
            wmma::mma_sync(acc[j], a_l, b_h, acc[j]);
            wmma::mma_sync(acc[j], a_h, b_l, acc[j]);
        }
    }
    __syncthreads();    // all A reads done; P overlay becomes safe

    #pragma unroll
    for (int j = 0; j < 7; ++j)
        wmma::store_matrix_sync(P + (size_t)(mtile * 16) * NPAD + n0 + j * 16,
                                acc[j], NPAD, wmma::mem_row_major);
    __syncthreads();

    // ---- phase 6: epilogue per u row ----
    float bb2 = b2[0];
    for (int u = wid; u < U1N; u += 16) {
        const float* row = P + (size_t)u * NPAD;
        float wu = T->s_w[u];
        float s = 0.f;
        #pragma unroll
        for (int j = 0; j < 7; ++j) {
            int o = lane + 32 * j;
            float x = row[o] + T->s_base[o] + wu * T->s_w1r0[o];
            s += fmaxf(x, 0.f) * T->s_w2[o];
        }
        #pragma unroll
        for (int off = 16; off; off >>= 1)
            s += __shfl_xor_sync(0xffffffffu, s, off);
        if (lane == 0) T->s_pi[u] = s + bb2;
    }
    __syncthreads();

    // ---- mask (dtype-adaptive) ----
    if (tid < U1N) {
        bool mv;
        if (g_mask_is_i32)
            mv = ((const int*)mask)[b * U1N + tid] != 0;
        else
            mv = ((const unsigned char*)mask)[b * U1N + tid] != 0;
        if (mv) T->s_pi[tid] = -1000000.0f;
    }
    __syncthreads();

    // ---- log_softmax + argmax (warp 0) ----
    if (wid == 0) {
        float mv = -3.4e38f; int mi = U1N;
        for (int u = lane; u < U1N; u += 32) {
            float v = T->s_pi[u];
            if (v > mv) { mv = v; mi = u; }
        }
        #pragma unroll
        for (int off = 16; off; off >>= 1) {
            float ov = __shfl_xor_sync(0xffffffffu, mv, off);
            int   oi = __shfl_xor_sync(0xffffffffu, mi, off);
            if (ov > mv || (ov == mv && oi < mi)) { mv = ov; mi = oi; }
        }
        float se = 0.f;
        for (int u = lane; u < U1N; u += 32) se += expf(T->s_pi[u] - mv);
        #pragma unroll
        for (int off = 16; off; off >>= 1)
            se += __shfl_xor_sync(0xffffffffu, se, off);
        if (lane == 0) { T->s_lse = mv + logf(se); T->s_sel_idx = mi; }
    }
    __syncthreads();

    float lse = T->s_lse;
    if (mode == 0) {
        for (int u = tid; u < U1N; u += 512)
            out[b * U1N + u] = T->s_pi[u] - lse;
    } else if (mode == 1) {
        if (tid == 0) out[b] = (float)T->s_sel_idx;
        float* op = out + BB;
        for (int u = tid; u < U1N; u += 512)
            op[b * U1N + u] = T->s_pi[u] - lse;
    } else {
        if (tid == 0) ((int*)out)[b] = T->s_sel_idx;
    }
}

// ---------------------------------------------------------------------------
extern "C" void kernel_launch(void* const* d_in, const int* in_sizes, int n_in,
                              void* d_out, int out_size)
{
    const float* emb  = (const float*)d_in[0];
    const float* w    = (const float*)d_in[1];
    const float* W_sc = (const float*)d_in[2];
    const float* b_sc = (const float*)d_in[3];
    const float* W1   = (const float*)d_in[4];
    const float* b1   = (const float*)d_in[5];
    const float* W2   = (const float*)d_in[6];
    const float* b2   = (const float*)d_in[7];
    const int*   seq  = (const int*)d_in[8];
    const void*  mask = d_in[9];

    int mode = 1;
    if (out_size == BB * U1N) mode = 0;
    else if (out_size == BB)  mode = 2;

    static int smem_sz = 0;
    if (!smem_sz) {
        smem_sz = OFF_TAIL + (int)sizeof(Tail);
        cudaFuncSetAttribute(fused_kernel,
                             cudaFuncAttributeMaxDynamicSharedMemorySize, smem_sz);
    }

    flag_init_kernel<<<1, 1>>>();
    mask_detect_kernel<<<208, 256>>>((const unsigned*)mask);
    w1bf_kernel<<<(NPAD * DN + 255) / 256, 256>>>(W1);
    fused_kernel<<<BB, 512, smem_sz>>>(emb, w, W_sc, b_sc, W1, b1, W2, b2,
                                       seq, mask, (float*)d_out, mode);
}